// round 4
// baseline (speedup 1.0000x reference)
#include <cuda_runtime.h>
#include <math.h>

// 2-layer LSTM, H=512, B=16, persistent kernel, grid-wide software barrier.
// 128 CTAs; CTA c owns h-indices [4c, 4c+4) => 16 gate rows per layer
// (rows j = g*512 + 4c + l for gate g in {i,f,g,o}, l in 0..3).
// Weights live in shared memory for the whole sequence.

#define NCTA  128
#define NTHR  256
#define HD    512
#define BQ    16
#define SP    516           // padded row stride (floats) for bank-conflict-free float4 loads
#define NROWS 16

__device__ __align__(16) float g_h1[BQ * HD];
__device__ __align__(16) float g_h2[BQ * HD];
__device__ unsigned g_bar_count = 0;
__device__ unsigned g_bar_gen   = 0;

__device__ __forceinline__ float sigmoidf_(float x) { return 1.0f / (1.0f + expf(-x)); }

__device__ __forceinline__ void grid_barrier() {
    __threadfence();
    __syncthreads();
    if (threadIdx.x == 0) {
        unsigned gen = *(volatile unsigned*)&g_bar_gen;
        if (atomicAdd(&g_bar_count, 1u) == NCTA - 1u) {
            atomicExch(&g_bar_count, 0u);
            __threadfence();
            atomicExch(&g_bar_gen, gen + 1u);
        } else {
            while (*(volatile unsigned*)&g_bar_gen == gen) { }
        }
    }
    __syncthreads();
    __threadfence();
}

__global__ void __launch_bounds__(NTHR, 1) lstm_kernel(
    const float* __restrict__ input,
    const float* __restrict__ Wih1, const float* __restrict__ Whh1,
    const float* __restrict__ bih1, const float* __restrict__ bhh1,
    const float* __restrict__ Wih2, const float* __restrict__ Whh2,
    const float* __restrict__ bih2, const float* __restrict__ bhh2,
    const float* __restrict__ Wout, const float* __restrict__ bout,
    float* __restrict__ out, int T)
{
    extern __shared__ float sm[];
    float* W1    = sm;                    // [16][SP]  Whh1 slice
    float* W2A   = W1  + NROWS * SP;      // [16][SP]  Wih2 slice
    float* W2B   = W2A + NROWS * SP;      // [16][SP]  Whh2 slice
    float* HB1   = W2B + NROWS * SP;      // [16][SP]  h1 (all batches)
    float* HB2   = HB1 + BQ * SP;         // [16][SP]  h2 (all batches)
    float* PART  = HB2 + BQ * SP;         // [2][16][17] partial gate sums
    float* BIAS1 = PART + 2 * 16 * 17;    // [16]
    float* BIAS2 = BIAS1 + 16;            // [16]
    float* WI1   = BIAS2 + 16;            // [16][2]
    float* C1S   = WI1 + 32;              // [4][16]
    float* C2S   = C1S + 64;              // [4][16]
    float* XS    = C2S + 64;              // [2][16]

    const int tid   = threadIdx.x;
    const int cta   = blockIdx.x;
    const int hbase = cta * 4;

    // ---- preamble: stage weights for our 16 rows (per layer) into smem ----
    for (int idx = tid; idx < NROWS * 128; idx += NTHR) {
        int r  = idx >> 7;
        int k4 = idx & 127;
        int g = r >> 2, l = r & 3;
        int j = g * HD + hbase + l;
        ((float4*)(W1  + r * SP))[k4] = ((const float4*)(Whh1 + (size_t)j * HD))[k4];
        ((float4*)(W2A + r * SP))[k4] = ((const float4*)(Wih2 + (size_t)j * HD))[k4];
        ((float4*)(W2B + r * SP))[k4] = ((const float4*)(Whh2 + (size_t)j * HD))[k4];
    }
    if (tid < 16) {
        int r = tid, g = r >> 2, l = r & 3;
        int j = g * HD + hbase + l;
        BIAS1[r] = bih1[j] + bhh1[j];
        BIAS2[r] = bih2[j] + bhh2[j];
        WI1[2 * r]     = Wih1[2 * j];
        WI1[2 * r + 1] = Wih1[2 * j + 1];
    }
    for (int idx = tid; idx < BQ * SP; idx += NTHR) { HB1[idx] = 0.0f; HB2[idx] = 0.0f; }
    if (tid < 64) { C1S[tid] = 0.0f; C2S[tid] = 0.0f; }
    const float bo = bout[0];
    __syncthreads();

    // warp work decomposition:
    //   khalf = warp>>2 selects K-half (layer1) / weight matrix (layer2)
    //   rg    = warp&3  selects a group of 4 rows
    //   lanes 0-15: batch=lane, rows (rg*4+0, rg*4+1)
    //   lanes16-31: batch=lane-16, rows (rg*4+2, rg*4+3)
    const int warp  = tid >> 5, lane = tid & 31;
    const int bq    = lane & 15;
    const int rp    = lane >> 4;
    const int rg    = warp & 3;
    const int khalf = warp >> 2;
    const int rowA  = rg * 4 + rp * 2;
    const int rowB  = rowA + 1;

    for (int t = 0; t < T; ++t) {
        // ---------------- Phase A: layer 1 ----------------
        if (tid < 32) {
            int b = tid & 15, c = tid >> 4;
            XS[c * 16 + b] = input[((size_t)b * T + t) * 2 + c];
        }
        __syncthreads();

        {   // gates1 partial: Whh1 slice @ h1_prev (K=512 split in two halves)
            const float4* wa = (const float4*)(W1 + rowA * SP + khalf * 256);
            const float4* wb = (const float4*)(W1 + rowB * SP + khalf * 256);
            const float4* uu = (const float4*)(HB1 + bq * SP + khalf * 256);
            float a0 = 0.0f, a1 = 0.0f;
            #pragma unroll 8
            for (int i = 0; i < 64; ++i) {
                float4 A = wa[i], Bv = wb[i], U = uu[i];
                a0 = fmaf(A.x,  U.x, a0); a0 = fmaf(A.y,  U.y, a0);
                a0 = fmaf(A.z,  U.z, a0); a0 = fmaf(A.w,  U.w, a0);
                a1 = fmaf(Bv.x, U.x, a1); a1 = fmaf(Bv.y, U.y, a1);
                a1 = fmaf(Bv.z, U.z, a1); a1 = fmaf(Bv.w, U.w, a1);
            }
            PART[khalf * 272 + rowA * 17 + bq] = a0;
            PART[khalf * 272 + rowB * 17 + bq] = a1;
        }
        __syncthreads();

        if (tid < 64) {  // update c1, h1 for our 4 h-indices x 16 batches
            int l = tid >> 4, b = tid & 15;
            float x0 = XS[b], x1 = XS[16 + b];
            float gi = PART[(l     ) * 17 + b] + PART[272 + (l     ) * 17 + b]
                     + BIAS1[l]      + WI1[2 * (l)          ] * x0 + WI1[2 * (l)           + 1] * x1;
            float gf = PART[(4 + l ) * 17 + b] + PART[272 + (4 + l ) * 17 + b]
                     + BIAS1[4 + l]  + WI1[2 * (4 + l)      ] * x0 + WI1[2 * (4 + l)       + 1] * x1;
            float gg = PART[(8 + l ) * 17 + b] + PART[272 + (8 + l ) * 17 + b]
                     + BIAS1[8 + l]  + WI1[2 * (8 + l)      ] * x0 + WI1[2 * (8 + l)       + 1] * x1;
            float go = PART[(12 + l) * 17 + b] + PART[272 + (12 + l) * 17 + b]
                     + BIAS1[12 + l] + WI1[2 * (12 + l)     ] * x0 + WI1[2 * (12 + l)      + 1] * x1;
            float iv = sigmoidf_(gi);
            float fv = sigmoidf_(gf);
            float gv = tanhf(gg);
            float ov = sigmoidf_(go);
            float c  = fv * C1S[l * 16 + b] + iv * gv;
            C1S[l * 16 + b] = c;
            float h = ov * tanhf(c);
            g_h1[b * HD + hbase + l] = h;
        }
        grid_barrier();

        // ---------------- Phase B: layer 2 ----------------
        // reload full h1(t) into smem
        for (int idx = tid; idx < BQ * 128; idx += NTHR) {
            int b = idx >> 7, k4 = idx & 127;
            ((float4*)(HB1 + b * SP))[k4] = ((const float4*)(g_h1 + b * HD))[k4];
        }
        __syncthreads();

        {   // gates2 partial: warps 0-3: Wih2 @ h1(t); warps 4-7: Whh2 @ h2(t-1)
            const float* Wsrc = khalf ? W2B : W2A;
            const float* Usrc = khalf ? HB2 : HB1;
            const float4* wa = (const float4*)(Wsrc + rowA * SP);
            const float4* wb = (const float4*)(Wsrc + rowB * SP);
            const float4* uu = (const float4*)(Usrc + bq * SP);
            float a0 = 0.0f, a1 = 0.0f;
            #pragma unroll 8
            for (int i = 0; i < 128; ++i) {
                float4 A = wa[i], Bv = wb[i], U = uu[i];
                a0 = fmaf(A.x,  U.x, a0); a0 = fmaf(A.y,  U.y, a0);
                a0 = fmaf(A.z,  U.z, a0); a0 = fmaf(A.w,  U.w, a0);
                a1 = fmaf(Bv.x, U.x, a1); a1 = fmaf(Bv.y, U.y, a1);
                a1 = fmaf(Bv.z, U.z, a1); a1 = fmaf(Bv.w, U.w, a1);
            }
            PART[khalf * 272 + rowA * 17 + bq] = a0;
            PART[khalf * 272 + rowB * 17 + bq] = a1;
        }
        __syncthreads();

        if (tid < 64) {  // update c2, h2
            int l = tid >> 4, b = tid & 15;
            float gi = PART[(l     ) * 17 + b] + PART[272 + (l     ) * 17 + b] + BIAS2[l];
            float gf = PART[(4 + l ) * 17 + b] + PART[272 + (4 + l ) * 17 + b] + BIAS2[4 + l];
            float gg = PART[(8 + l ) * 17 + b] + PART[272 + (8 + l ) * 17 + b] + BIAS2[8 + l];
            float go = PART[(12 + l) * 17 + b] + PART[272 + (12 + l) * 17 + b] + BIAS2[12 + l];
            float iv = sigmoidf_(gi);
            float fv = sigmoidf_(gf);
            float gv = tanhf(gg);
            float ov = sigmoidf_(go);
            float c  = fv * C2S[l * 16 + b] + iv * gv;
            C2S[l * 16 + b] = c;
            float h = ov * tanhf(c);
            g_h2[b * HD + hbase + l] = h;
        }
        grid_barrier();

        // output head: CTA b (b<16), warp 0 computes out[b][t] = h2[b] . Wout + bout
        if (cta < BQ && warp == 0) {
            float s = 0.0f;
            const float* h2p = g_h2 + cta * HD;
            for (int k = lane; k < HD; k += 32) s += h2p[k] * Wout[k];
            #pragma unroll
            for (int o = 16; o; o >>= 1) s += __shfl_xor_sync(0xffffffffu, s, o);
            if (lane == 0) out[(size_t)cta * T + t] = s + bo;
        }
        // reload h2(t) into smem for next step's phase B
        for (int idx = tid; idx < BQ * 128; idx += NTHR) {
            int b = idx >> 7, k4 = idx & 127;
            ((float4*)(HB2 + b * SP))[k4] = ((const float4*)(g_h2 + b * HD))[k4];
        }
        __syncthreads();
    }
}

extern "C" void kernel_launch(void* const* d_in, const int* in_sizes, int n_in,
                              void* d_out, int out_size)
{
    const float* input = (const float*)d_in[0];
    const float* Wih1  = (const float*)d_in[1];
    const float* Whh1  = (const float*)d_in[2];
    const float* bih1  = (const float*)d_in[3];
    const float* bhh1  = (const float*)d_in[4];
    const float* Wih2  = (const float*)d_in[5];
    const float* Whh2  = (const float*)d_in[6];
    const float* bih2  = (const float*)d_in[7];
    const float* bhh2  = (const float*)d_in[8];
    const float* Wout  = (const float*)d_in[9];
    const float* bout  = (const float*)d_in[10];

    int T = in_sizes[0] / (BQ * 2);

    size_t smem_floats = 3 * NROWS * SP   // W1, W2A, W2B
                       + 2 * BQ * SP      // HB1, HB2
                       + 2 * 16 * 17      // PART
                       + 16 + 16 + 32     // BIAS1, BIAS2, WI1
                       + 64 + 64 + 32;    // C1S, C2S, XS
    size_t smem_bytes = smem_floats * sizeof(float);

    cudaFuncSetAttribute(lstm_kernel, cudaFuncAttributeMaxDynamicSharedMemorySize,
                         (int)smem_bytes);

    lstm_kernel<<<NCTA, NTHR, smem_bytes>>>(
        input, Wih1, Whh1, bih1, bhh1, Wih2, Whh2, bih2, bhh2, Wout, bout,
        (float*)d_out, T);
}

// round 7
// speedup vs baseline: 1.9098x; 1.9098x over previous
#include <cuda_runtime.h>
#include <math.h>

// 2-layer LSTM H=512 B=16 T=6574. Persistent kernel, 128 CTAs x 256 thr.
// CTA owns h-indices [4c,4c+4) = 16 gate rows/layer. Weights register-resident:
//   warps 0-3: Whh1 rows (lane r=lane&15, k-chunk 64 at (warp&3)*128+s*64)
//   warps 4-7: Whh2 rows (same mapping)
//   all warps: Wih2 rows (k-chunk 32 at warp*64+s*32)
// h vectors in smem, read as 16-lane broadcast LDS.128; math in fma.rn.f32x2.
// Grid barrier: proven R3 atomic-counter barrier (replay-safe, no init kernel).

#define NCTA 128
#define NTHR 256
#define HD   512
#define BQ   16
#define PSTR 288      // floats per partial slot (16 rows * 18)
#define RSTR 18

typedef unsigned long long u64;

__device__ __align__(16) float g_h1[BQ * HD];
__device__ __align__(16) float g_h2[BQ * HD];
__device__ unsigned g_bar_count = 0;
__device__ unsigned g_bar_gen   = 0;

__device__ __forceinline__ void ffma2(u64& d, u64 a, u64 b) {
    asm("fma.rn.f32x2 %0, %1, %2, %0;" : "+l"(d) : "l"(a), "l"(b));
}
__device__ __forceinline__ float f2sum(u64 a) {
    float lo, hi;
    asm("mov.b64 {%0,%1}, %2;" : "=f"(lo), "=f"(hi) : "l"(a));
    return lo + hi;
}
__device__ __forceinline__ float sigmoidf_(float x) { return 1.0f / (1.0f + expf(-x)); }

__device__ __forceinline__ float4 ldcg_f4(const float4* p) {
    float4 v;
    asm volatile("ld.global.cg.v4.f32 {%0,%1,%2,%3}, [%4];"
                 : "=f"(v.x), "=f"(v.y), "=f"(v.z), "=f"(v.w) : "l"(p) : "memory");
    return v;
}
__device__ __forceinline__ float ldcg_f32(const float* p) {
    float v;
    asm volatile("ld.global.cg.f32 %0, [%1];" : "=f"(v) : "l"(p) : "memory");
    return v;
}

// Proven grid barrier (R3): atomic counter + generation flip. Replay-safe:
// gen is only compared for *change*, count self-resets to 0.
__device__ __forceinline__ void grid_barrier() {
    __threadfence();
    __syncthreads();
    if (threadIdx.x == 0) {
        unsigned gen = *(volatile unsigned*)&g_bar_gen;
        if (atomicAdd(&g_bar_count, 1u) == NCTA - 1u) {
            atomicExch(&g_bar_count, 0u);
            __threadfence();
            atomicExch(&g_bar_gen, gen + 1u);
        } else {
            while (*(volatile unsigned*)&g_bar_gen == gen) { }
        }
    }
    __syncthreads();
    __threadfence();
}

// GEMV partial: lane owns one row r (weights w, NJ ulonglong2 = 4*NJ k's) and
// accumulates over all 16 batches, 2 at a time. h reads are 16-lane broadcasts.
template <int NJ>
__device__ __forceinline__ void gemv_part(const u64* __restrict__ w,
                                          const float* __restrict__ HB,
                                          int koff, float* __restrict__ pdst) {
    for (int b2 = 0; b2 < 8; ++b2) {
        const ulonglong2* h0 = (const ulonglong2*)(HB + (2 * b2) * HD + koff);
        const ulonglong2* h1 = (const ulonglong2*)(HB + (2 * b2 + 1) * HD + koff);
        u64 a0 = 0, a1 = 0;
#pragma unroll
        for (int i = 0; i < NJ; ++i) {
            ulonglong2 v0 = h0[i];
            ulonglong2 v1 = h1[i];
            ffma2(a0, w[2 * i], v0.x); ffma2(a0, w[2 * i + 1], v0.y);
            ffma2(a1, w[2 * i], v1.x); ffma2(a1, w[2 * i + 1], v1.y);
        }
        float r0 = f2sum(a0), r1 = f2sum(a1);
        u64 pk;
        asm("mov.b64 %0, {%1,%2};" : "=l"(pk) : "f"(r0), "f"(r1));
        *(u64*)(pdst + 2 * b2) = pk;
    }
}

__global__ void __launch_bounds__(NTHR, 1) lstm_kernel(
    const float* __restrict__ input,
    const float* __restrict__ Wih1, const float* __restrict__ Whh1,
    const float* __restrict__ bih1, const float* __restrict__ bhh1,
    const float* __restrict__ Wih2, const float* __restrict__ Whh2,
    const float* __restrict__ bih2, const float* __restrict__ bhh2,
    const float* __restrict__ Wout, const float* __restrict__ bout,
    float* __restrict__ out, int T)
{
    extern __shared__ float sm[];
    float* HB1   = sm;                  // [16][512] h1
    float* HB2   = HB1 + BQ * HD;       // [16][512] h2
    float* PART1 = HB2 + BQ * HD;       // [8][288]
    float* PART2 = PART1 + 8 * PSTR;    // [24][288]
    float* GVAL  = PART2 + 24 * PSTR;   // [256] gate sums [r][b]
    float* BIAS1 = GVAL + 256;          // [16]
    float* BIAS2 = BIAS1 + 16;          // [16]
    float* WI1s  = BIAS2 + 16;          // [16][2]
    float* XS    = WI1s + 32;           // [2][16]
    float* C1S   = XS + 32;             // [64]
    float* C2S   = C1S + 64;            // [64]
    float* WoutS = C2S + 64;            // [512]

    const int tid  = threadIdx.x;
    const int cta  = blockIdx.x;
    const int warp = tid >> 5, lane = tid & 31;
    const int r    = lane & 15, s = lane >> 4;
    const int hbase = cta * 4;
    const int jrow = (r >> 2) * HD + hbase + (r & 3);

    // ---- weight preload into registers ----
    const float* WAsrc = (warp < 4) ? Whh1 : Whh2;
    const int koffA = (warp & 3) * 128 + s * 64;
    u64 wA[32];
    {
        const u64* gp = (const u64*)(WAsrc + (size_t)jrow * HD + koffA);
#pragma unroll
        for (int i = 0; i < 32; ++i) wA[i] = gp[i];
    }
    const int koffB = warp * 64 + s * 32;
    u64 wB[16];
    {
        const u64* gp = (const u64*)(Wih2 + (size_t)jrow * HD + koffB);
#pragma unroll
        for (int i = 0; i < 16; ++i) wB[i] = gp[i];
    }

    // ---- misc preamble ----
    if (tid < 16) {
        int jt = (tid >> 2) * HD + hbase + (tid & 3);
        BIAS1[tid] = bih1[jt] + bhh1[jt];
        BIAS2[tid] = bih2[jt] + bhh2[jt];
        WI1s[2 * tid]     = Wih1[2 * jt];
        WI1s[2 * tid + 1] = Wih1[2 * jt + 1];
    }
    for (int i = tid; i < BQ * HD; i += NTHR) { HB1[i] = 0.0f; HB2[i] = 0.0f; }
    for (int i = tid; i < HD; i += NTHR) WoutS[i] = Wout[i];
    if (tid < 64) { C1S[tid] = 0.0f; C2S[tid] = 0.0f; }
    const float bo = bout[0];
    __syncthreads();

    float* pdstA = ((warp < 4) ? PART1 : PART2) + ((warp & 3) * 2 + s) * PSTR + r * RSTR;
    float* pdstB = PART2 + (8 + warp * 2 + s) * PSTR + r * RSTR;
    const float* HBA = (warp < 4) ? HB1 : HB2;

    for (int t = 0; t < T; ++t) {
        // x(t) staged while GEMV runs (visible after next __syncthreads)
        if (tid < 32) {
            int b = tid & 15, c = tid >> 4;
            XS[c * 16 + b] = input[((size_t)b * T + t) * 2 + c];
        }

        // Phase A: warps 0-3: Whh1 @ h1(t-1); warps 4-7: Whh2 @ h2(t-1)
        gemv_part<16>(wA, HBA, koffA, pdstA);
        __syncthreads();

        // layer-1 gate sums (warps 4-7's partials live in PART2, untouched)
        {
            int rr = tid >> 4, b = tid & 15;
            float sum = BIAS1[rr] + WI1s[2 * rr] * XS[b] + WI1s[2 * rr + 1] * XS[16 + b];
#pragma unroll
            for (int p = 0; p < 8; ++p) sum += PART1[p * PSTR + rr * RSTR + b];
            GVAL[rr * 16 + b] = sum;
        }
        __syncthreads();

        if (tid < 64) {   // layer-1 cell update for 4 h-indices x 16 batches
            int l = tid >> 4, b = tid & 15;
            float gi = GVAL[(l) * 16 + b];
            float gf = GVAL[(4 + l) * 16 + b];
            float gc = GVAL[(8 + l) * 16 + b];
            float go = GVAL[(12 + l) * 16 + b];
            float iv = sigmoidf_(gi), fv = sigmoidf_(gf);
            float cv = tanhf(gc), ov = sigmoidf_(go);
            float c = fv * C1S[tid] + iv * cv;
            C1S[tid] = c;
            g_h1[b * HD + hbase + l] = ov * tanhf(c);
        }
        grid_barrier();

        // reload full h1(t) into smem: 16*512 floats = 2048 float4 = 8 * NTHR
        {
            const float4* src = (const float4*)g_h1;
            float4* dst = (float4*)HB1;
#pragma unroll
            for (int i = 0; i < 8; ++i) dst[tid + i * NTHR] = ldcg_f4(src + tid + i * NTHR);
        }
        __syncthreads();

        // Phase C: all 8 warps: Wih2 @ h1(t)
        gemv_part<8>(wB, HB1, koffB, pdstB);
        __syncthreads();

        // layer-2 gate sums: 8 Whh2 partials + 16 Wih2 partials
        {
            int rr = tid >> 4, b = tid & 15;
            float sum = BIAS2[rr];
#pragma unroll
            for (int p = 0; p < 24; ++p) sum += PART2[p * PSTR + rr * RSTR + b];
            GVAL[rr * 16 + b] = sum;
        }
        __syncthreads();

        if (tid < 64) {   // layer-2 cell update
            int l = tid >> 4, b = tid & 15;
            float gi = GVAL[(l) * 16 + b];
            float gf = GVAL[(4 + l) * 16 + b];
            float gc = GVAL[(8 + l) * 16 + b];
            float go = GVAL[(12 + l) * 16 + b];
            float iv = sigmoidf_(gi), fv = sigmoidf_(gf);
            float cv = tanhf(gc), ov = sigmoidf_(go);
            float c = fv * C2S[tid] + iv * cv;
            C2S[tid] = c;
            g_h2[b * HD + hbase + l] = ov * tanhf(c);
        }
        grid_barrier();

        // output head: CTA b<16, warp 0: out[b][t] = h2[b] . Wout + bout
        if (cta < BQ && warp == 0) {
            float ssum = 0.0f;
            const float* h2p = g_h2 + cta * HD;
#pragma unroll
            for (int k = 0; k < 16; ++k)
                ssum += ldcg_f32(h2p + lane + k * 32) * WoutS[lane + k * 32];
#pragma unroll
            for (int o = 16; o; o >>= 1) ssum += __shfl_xor_sync(0xffffffffu, ssum, o);
            if (lane == 0) out[(size_t)cta * T + t] = ssum + bo;
        }

        // reload h2(t) into smem for next step's phase A: 2048 float4 = 8 * NTHR
        {
            const float4* src = (const float4*)g_h2;
            float4* dst = (float4*)HB2;
#pragma unroll
            for (int i = 0; i < 8; ++i) dst[tid + i * NTHR] = ldcg_f4(src + tid + i * NTHR);
        }
        __syncthreads();
    }
}

extern "C" void kernel_launch(void* const* d_in, const int* in_sizes, int n_in,
                              void* d_out, int out_size)
{
    const float* input = (const float*)d_in[0];
    const float* Wih1  = (const float*)d_in[1];
    const float* Whh1  = (const float*)d_in[2];
    const float* bih1  = (const float*)d_in[3];
    const float* bhh1  = (const float*)d_in[4];
    const float* Wih2  = (const float*)d_in[5];
    const float* Whh2  = (const float*)d_in[6];
    const float* bih2  = (const float*)d_in[7];
    const float* bhh2  = (const float*)d_in[8];
    const float* Wout  = (const float*)d_in[9];
    const float* bout  = (const float*)d_in[10];

    int T = in_sizes[0] / (BQ * 2);

    size_t smem_floats = 2 * BQ * HD          // HB1, HB2
                       + 8 * PSTR + 24 * PSTR // PART1, PART2
                       + 256                  // GVAL
                       + 16 + 16 + 32 + 32    // BIAS1, BIAS2, WI1, XS
                       + 64 + 64 + HD;        // C1S, C2S, WoutS
    size_t smem_bytes = smem_floats * sizeof(float);

    cudaFuncSetAttribute(lstm_kernel, cudaFuncAttributeMaxDynamicSharedMemorySize,
                         (int)smem_bytes);

    lstm_kernel<<<NCTA, NTHR, smem_bytes>>>(
        input, Wih1, Whh1, bih1, bhh1, Wih2, Whh2, bih2, bhh2, Wout, bout,
        (float*)d_out, T);
}

// round 11
// speedup vs baseline: 2.7540x; 1.4420x over previous
#include <cuda_runtime.h>
#include <math.h>

// 2-layer LSTM H=512 B=16 T=6574. Persistent kernel, 128 CTAs x 256 thr.
// CTA owns h-indices [4c,4c+4) = 16 gate rows/layer. Weights register-resident.
// SOFTWARE-PIPELINED: interval k computes h1(k) AND h2(k-1) concurrently
// (layer 2 lags one step) -> ONE grid barrier per step.
// Cross-CTA h state is DOUBLE-BUFFERED by interval parity so the single
// barrier is race-free; k=0 publishes zeros for h2(-1) (replay-deterministic).

#define NCTA 128
#define NTHR 256
#define HD   512
#define BQ   16
#define PSTR 288      // floats per partial slot (16 rows * 18)
#define RSTR 18

typedef unsigned long long u64;

__device__ __align__(16) float g_h1[2][BQ * HD];
__device__ __align__(16) float g_h2[2][BQ * HD];
__device__ unsigned g_bar_count = 0;
__device__ unsigned g_bar_gen   = 0;

__device__ __forceinline__ void ffma2(u64& d, u64 a, u64 b) {
    asm("fma.rn.f32x2 %0, %1, %2, %0;" : "+l"(d) : "l"(a), "l"(b));
}
__device__ __forceinline__ float f2sum(u64 a) {
    float lo, hi;
    asm("mov.b64 {%0,%1}, %2;" : "=f"(lo), "=f"(hi) : "l"(a));
    return lo + hi;
}
__device__ __forceinline__ float sigmoidf_(float x) { return 1.0f / (1.0f + expf(-x)); }

__device__ __forceinline__ float4 ldcg_f4(const float4* p) {
    float4 v;
    asm volatile("ld.global.cg.v4.f32 {%0,%1,%2,%3}, [%4];"
                 : "=f"(v.x), "=f"(v.y), "=f"(v.z), "=f"(v.w) : "l"(p) : "memory");
    return v;
}

// Proven grid barrier (R3): atomic counter + generation flip. Replay-safe.
__device__ __forceinline__ void grid_barrier() {
    __threadfence();
    __syncthreads();
    if (threadIdx.x == 0) {
        unsigned gen = *(volatile unsigned*)&g_bar_gen;
        if (atomicAdd(&g_bar_count, 1u) == NCTA - 1u) {
            atomicExch(&g_bar_count, 0u);
            __threadfence();
            atomicExch(&g_bar_gen, gen + 1u);
        } else {
            while (*(volatile unsigned*)&g_bar_gen == gen) { }
        }
    }
    __syncthreads();
    __threadfence();
}

// GEMV partial: lane owns one row (weights w, 4*NJ k's), accumulates over all
// 16 batches, 2 at a time. h reads are 16-lane broadcast LDS.128.
template <int NJ>
__device__ __forceinline__ void gemv_part(const u64* __restrict__ w,
                                          const float* __restrict__ HB,
                                          int koff, float* __restrict__ pdst) {
    for (int b2 = 0; b2 < 8; ++b2) {
        const ulonglong2* h0 = (const ulonglong2*)(HB + (2 * b2) * HD + koff);
        const ulonglong2* h1 = (const ulonglong2*)(HB + (2 * b2 + 1) * HD + koff);
        u64 a0 = 0, a1 = 0;
#pragma unroll
        for (int i = 0; i < NJ; ++i) {
            ulonglong2 v0 = h0[i];
            ulonglong2 v1 = h1[i];
            ffma2(a0, w[2 * i], v0.x); ffma2(a0, w[2 * i + 1], v0.y);
            ffma2(a1, w[2 * i], v1.x); ffma2(a1, w[2 * i + 1], v1.y);
        }
        float r0 = f2sum(a0), r1 = f2sum(a1);
        u64 pk;
        asm("mov.b64 %0, {%1,%2};" : "=l"(pk) : "f"(r0), "f"(r1));
        *(u64*)(pdst + 2 * b2) = pk;
    }
}

__global__ void __launch_bounds__(NTHR, 1) lstm_kernel(
    const float* __restrict__ input,
    const float* __restrict__ Wih1, const float* __restrict__ Whh1,
    const float* __restrict__ bih1, const float* __restrict__ bhh1,
    const float* __restrict__ Wih2, const float* __restrict__ Whh2,
    const float* __restrict__ bih2, const float* __restrict__ bhh2,
    const float* __restrict__ Wout, const float* __restrict__ bout,
    float* __restrict__ out, int T)
{
    extern __shared__ float sm[];
    float* HB1   = sm;                  // [16][512] h1(k-1)
    float* HB2   = HB1 + BQ * HD;       // [16][512] h2(k-2)
    float* PART1 = HB2 + BQ * HD;       // [8][288]   layer-1 partials
    float* PART2 = PART1 + 8 * PSTR;    // [24][288]  layer-2 partials
    float* GVAL1 = PART2 + 24 * PSTR;   // [256]
    float* GVAL2 = GVAL1 + 256;         // [256]
    float* BIAS1 = GVAL2 + 256;         // [16]
    float* BIAS2 = BIAS1 + 16;          // [16]
    float* WI1s  = BIAS2 + 16;          // [16][2]
    float* XS    = WI1s + 32;           // [2][16]
    float* C1S   = XS + 32;             // [64]
    float* C2S   = C1S + 64;            // [64]
    float* WoutS = C2S + 64;            // [512]

    const int tid  = threadIdx.x;
    const int cta  = blockIdx.x;
    const int warp = tid >> 5, lane = tid & 31;
    const int r    = lane & 15, s = lane >> 4;
    const int hbase = cta * 4;
    const int jrow = (r >> 2) * HD + hbase + (r & 3);

    // ---- weight preload into registers ----
    const float* WAsrc = (warp < 4) ? Whh1 : Whh2;
    const int koffA = (warp & 3) * 128 + s * 64;
    u64 wA[32];
    {
        const u64* gp = (const u64*)(WAsrc + (size_t)jrow * HD + koffA);
#pragma unroll
        for (int i = 0; i < 32; ++i) wA[i] = gp[i];
    }
    const int koffB = warp * 64 + s * 32;
    u64 wB[16];
    {
        const u64* gp = (const u64*)(Wih2 + (size_t)jrow * HD + koffB);
#pragma unroll
        for (int i = 0; i < 16; ++i) wB[i] = gp[i];
    }

    // ---- misc preamble ----
    if (tid < 16) {
        int jt = (tid >> 2) * HD + hbase + (tid & 3);
        BIAS1[tid] = bih1[jt] + bhh1[jt];
        BIAS2[tid] = bih2[jt] + bhh2[jt];
        WI1s[2 * tid]     = Wih1[2 * jt];
        WI1s[2 * tid + 1] = Wih1[2 * jt + 1];
    }
    for (int i = tid; i < BQ * HD; i += NTHR) { HB1[i] = 0.0f; HB2[i] = 0.0f; }
    for (int i = tid; i < HD; i += NTHR) WoutS[i] = Wout[i];
    if (tid < 64) { C1S[tid] = 0.0f; C2S[tid] = 0.0f; }
    const float bo = bout[0];
    __syncthreads();

    float* pdstA = ((warp < 4) ? PART1 : PART2) + ((warp & 3) * 2 + s) * PSTR + r * RSTR;
    float* pdstB = PART2 + (8 + warp * 2 + s) * PSTR + r * RSTR;
    const float* HBA = (warp < 4) ? HB1 : HB2;

    // Pipelined intervals: k = 0..T. Interval k computes h1(k) (k<T) and
    // h2(k-1) (k>=1; k==0 publishes zeros), writes to parity buffer k&1,
    // ONE barrier, reloads HB1/HB2 from buffer k&1, emits out(k-1).
    for (int k = 0; k <= T; ++k) {
        const bool do_l1 = (k < T);
        const bool do_l2 = (k >= 1);
        const int  wr    = k & 1;

        // stage x(k) while GEMVs run (read after the next __syncthreads)
        if (do_l1 && tid < 32) {
            int b = tid & 15, c = tid >> 4;
            XS[c * 16 + b] = input[((size_t)b * T + k) * 2 + c];
        }

        // fused GEMV phase
        gemv_part<16>(wA, HBA, koffA, pdstA);   // w0-3: Whh1@h1(k-1); w4-7: Whh2@h2(k-2)
        gemv_part<8>(wB, HB1, koffB, pdstB);    // all: Wih2@h1(k-1)
        __syncthreads();

        // reductions for both layers (256 (row,b) pairs each)
        {
            int rr = tid >> 4, b = tid & 15;
            float s1 = BIAS1[rr] + WI1s[2 * rr] * XS[b] + WI1s[2 * rr + 1] * XS[16 + b];
#pragma unroll
            for (int p = 0; p < 8; ++p) s1 += PART1[p * PSTR + rr * RSTR + b];
            GVAL1[rr * 16 + b] = s1;
            float s2 = BIAS2[rr];
#pragma unroll
            for (int p = 0; p < 24; ++p) s2 += PART2[p * PSTR + rr * RSTR + b];
            GVAL2[rr * 16 + b] = s2;
        }
        __syncthreads();

        // both cell updates concurrently, publish into parity buffer wr
        if (tid < 64) {
            if (do_l1) {
                int l = tid >> 4, b = tid & 15;
                float gi = GVAL1[(l) * 16 + b];
                float gf = GVAL1[(4 + l) * 16 + b];
                float gc = GVAL1[(8 + l) * 16 + b];
                float go = GVAL1[(12 + l) * 16 + b];
                float iv = sigmoidf_(gi), fv = sigmoidf_(gf);
                float cv = tanhf(gc), ov = sigmoidf_(go);
                float c = fv * C1S[tid] + iv * cv;
                C1S[tid] = c;
                g_h1[wr][b * HD + hbase + l] = ov * tanhf(c);
            }
        } else if (tid < 128) {
            int u = tid - 64;
            int l = u >> 4, b = u & 15;
            if (do_l2) {
                float gi = GVAL2[(l) * 16 + b];
                float gf = GVAL2[(4 + l) * 16 + b];
                float gc = GVAL2[(8 + l) * 16 + b];
                float go = GVAL2[(12 + l) * 16 + b];
                float iv = sigmoidf_(gi), fv = sigmoidf_(gf);
                float cv = tanhf(gc), ov = sigmoidf_(go);
                float c = fv * C2S[u] + iv * cv;
                C2S[u] = c;
                g_h2[wr][b * HD + hbase + l] = ov * tanhf(c);
            } else {
                // k == 0: publish h2(-1) = 0 so replays are deterministic
                g_h2[wr][b * HD + hbase + l] = 0.0f;
            }
        }
        grid_barrier();

        // reload h1(k), h2(k-1) from parity buffer wr: 2*2048 float4
        {
            const float4* s1 = (const float4*)g_h1[wr];
            const float4* s2 = (const float4*)g_h2[wr];
            float4* d1 = (float4*)HB1;
            float4* d2 = (float4*)HB2;
#pragma unroll
            for (int i = 0; i < 8; ++i) d1[tid + i * NTHR] = ldcg_f4(s1 + tid + i * NTHR);
#pragma unroll
            for (int i = 0; i < 8; ++i) d2[tid + i * NTHR] = ldcg_f4(s2 + tid + i * NTHR);
        }
        __syncthreads();

        // output head: HB2 now holds h2(k-1); CTA b<16 emits out[b][k-1]
        if (do_l2 && cta < BQ && warp == 0) {
            float ssum = 0.0f;
            const float* h2p = HB2 + cta * HD;
#pragma unroll
            for (int q = 0; q < 16; ++q)
                ssum += h2p[lane + q * 32] * WoutS[lane + q * 32];
#pragma unroll
            for (int o = 16; o; o >>= 1) ssum += __shfl_xor_sync(0xffffffffu, ssum, o);
            if (lane == 0) out[(size_t)cta * T + (k - 1)] = ssum + bo;
        }
    }
}

extern "C" void kernel_launch(void* const* d_in, const int* in_sizes, int n_in,
                              void* d_out, int out_size)
{
    const float* input = (const float*)d_in[0];
    const float* Wih1  = (const float*)d_in[1];
    const float* Whh1  = (const float*)d_in[2];
    const float* bih1  = (const float*)d_in[3];
    const float* bhh1  = (const float*)d_in[4];
    const float* Wih2  = (const float*)d_in[5];
    const float* Whh2  = (const float*)d_in[6];
    const float* bih2  = (const float*)d_in[7];
    const float* bhh2  = (const float*)d_in[8];
    const float* Wout  = (const float*)d_in[9];
    const float* bout  = (const float*)d_in[10];

    int T = in_sizes[0] / (BQ * 2);

    size_t smem_floats = 2 * BQ * HD          // HB1, HB2
                       + 8 * PSTR + 24 * PSTR // PART1, PART2
                       + 256 + 256            // GVAL1, GVAL2
                       + 16 + 16 + 32 + 32    // BIAS1, BIAS2, WI1, XS
                       + 64 + 64 + HD;        // C1S, C2S, WoutS
    size_t smem_bytes = smem_floats * sizeof(float);

    cudaFuncSetAttribute(lstm_kernel, cudaFuncAttributeMaxDynamicSharedMemorySize,
                         (int)smem_bytes);

    lstm_kernel<<<NCTA, NTHR, smem_bytes>>>(
        input, Wih1, Whh1, bih1, bhh1, Wih2, Whh2, bih2, bhh2, Wout, bout,
        (float*)d_out, T);
}